// round 11
// baseline (speedup 1.0000x reference)
#include <cuda_runtime.h>
#include <cstdint>

// ---------------- problem constants ----------------
#define NB   4
#define SS   2048
#define EE   1024
#define NH   8
#define HD   128
#define ROWS 8192            // NB*SS
#define UN   4096            // (HD*2+AD*2)*H
#define EPSV 1e-6f
#define ALPHAV 0.08838834764831845f   // 1/sqrt(128)
#define INV_S (1.0f/2048.0f)

// ---------------- scratch (static device memory; allocation-free) ----------------
__device__ float g_xn[ROWS * EE];            // 32 MB  rounded normed x
__device__ float g_uvqk[(size_t)ROWS * UN];  // 128 MB u|v|q|k (u silu'd), tf32-rounded
__device__ float g_attn[ROWS * 1024];        // 32 MB  attention out, rounded
__device__ float g_gated[ROWS * 1024];       // 32 MB  u * LN(attn), rounded
__device__ float g_w1[EE * UN];              // 16 MB  rounded uvqk weight
__device__ float g_w2[3072 * 1024];          // 12 MB  rounded output weight

// ---------------- helpers ----------------
__device__ __forceinline__ float tf32r(float x) {
    uint32_t u; asm("cvt.rna.tf32.f32 %0, %1;" : "=r"(u) : "f"(x));
    return __uint_as_float(u);
}
__device__ __forceinline__ void cp16(void* dst, const void* src) {
    uint32_t d = (uint32_t)__cvta_generic_to_shared(dst);
    asm volatile("cp.async.cg.shared.global [%0], [%1], 16;\n" :: "r"(d), "l"(src));
}
__device__ __forceinline__ void cp_commit() { asm volatile("cp.async.commit_group;\n"); }
__device__ __forceinline__ void cp_wait0()  { asm volatile("cp.async.wait_group 0;\n"); }
__device__ __forceinline__ void cp_wait1()  { asm volatile("cp.async.wait_group 1;\n"); }

__device__ __forceinline__ void mma8(float* c, const uint32_t* a, const uint32_t* b) {
    asm volatile(
        "mma.sync.aligned.m16n8k8.row.col.f32.tf32.tf32.f32 "
        "{%0,%1,%2,%3},{%4,%5,%6,%7},{%8,%9},{%0,%1,%2,%3};\n"
        : "+f"(c[0]), "+f"(c[1]), "+f"(c[2]), "+f"(c[3])
        : "r"(a[0]), "r"(a[1]), "r"(a[2]), "r"(a[3]), "r"(b[0]), "r"(b[1]));
}

// ---------------- kernel 0: round weights to tf32 ----------------
__global__ void round_weights_k(const float4* __restrict__ w1, const float4* __restrict__ w2) {
    int i = blockIdx.x * 256 + threadIdx.x;
    const int n1 = EE * UN / 4;        // 1048576
    const int n2 = 3072 * 1024 / 4;    // 786432
    if (i < n1) {
        float4 v = w1[i];
        v.x = tf32r(v.x); v.y = tf32r(v.y); v.z = tf32r(v.z); v.w = tf32r(v.w);
        ((float4*)g_w1)[i] = v;
    }
    if (i < n2) {
        float4 v = w2[i];
        v.x = tf32r(v.x); v.y = tf32r(v.y); v.z = tf32r(v.z); v.w = tf32r(v.w);
        ((float4*)g_w2)[i] = v;
    }
}

// ---------------- kernel 1: input layernorm ----------------
__global__ __launch_bounds__(256) void ln_in_k(const float* __restrict__ x,
                                               const float* __restrict__ sc,
                                               const float* __restrict__ bi) {
    int row = blockIdx.x, t = threadIdx.x;
    const float* xr = x + (size_t)row * EE;
    float v[4]; float s = 0.f, s2 = 0.f;
#pragma unroll
    for (int i = 0; i < 4; i++) { v[i] = xr[t + i * 256]; s += v[i]; s2 += v[i] * v[i]; }
#pragma unroll
    for (int o = 16; o; o >>= 1) { s += __shfl_xor_sync(~0u, s, o); s2 += __shfl_xor_sync(~0u, s2, o); }
    __shared__ float rs[8], rq[8];
    if ((t & 31) == 0) { rs[t >> 5] = s; rq[t >> 5] = s2; }
    __syncthreads();
    s = 0.f; s2 = 0.f;
#pragma unroll
    for (int i = 0; i < 8; i++) { s += rs[i]; s2 += rq[i]; }
    float mu = s * (1.f / EE);
    float var = s2 * (1.f / EE) - mu * mu;
    float r = rsqrtf(var + EPSV);
#pragma unroll
    for (int i = 0; i < 4; i++) {
        int c = t + i * 256;
        g_xn[(size_t)row * EE + c] = tf32r((v[i] - mu) * r * sc[c] + bi[c]);
    }
}

// ---------------- kernel 2: uvqk GEMM (8192x1024 @ 1024x4096) ----------------
// BM=128 BN=128 BK=32, 256 thr, 8 warps (4m x 2n), warp tile 32x64
#define ASTR 36
#define BSTR 132
#define GEMM_SMEM ((2 * 128 * ASTR + 2 * 32 * BSTR) * 4)   // 70656 B

__global__ __launch_bounds__(256) void gemm_uvqk_k(const float* __restrict__ beta) {
    extern __shared__ float sm[];
    float* As = sm;                      // 2 stages * 128*36
    float* Bs = sm + 2 * 128 * ASTR;     // 2 stages * 32*132
    const int tid = threadIdx.x, lane = tid & 31, w = tid >> 5;
    const int wm = w & 3, wn = w >> 2;
    const int bm = blockIdx.y, bn = blockIdx.x;

    float acc[2][8][4];
#pragma unroll
    for (int i = 0; i < 2; i++)
#pragma unroll
        for (int j = 0; j < 8; j++)
#pragma unroll
            for (int e = 0; e < 4; e++) acc[i][j][e] = 0.f;

    auto issue = [&](int kb, int stg) {
        float* as = As + stg * 128 * ASTR;
        float* bs = Bs + stg * 32 * BSTR;
#pragma unroll
        for (int i = 0; i < 4; i++) {
            int c = tid + i * 256; int r = c >> 3, k4 = c & 7;
            cp16(as + r * ASTR + k4 * 4, g_xn + (size_t)(bm * 128 + r) * EE + kb * 32 + k4 * 4);
        }
#pragma unroll
        for (int i = 0; i < 4; i++) {
            int c = tid + i * 256; int kr = c >> 5, n4 = c & 31;
            cp16(bs + kr * BSTR + n4 * 4, g_w1 + (size_t)(kb * 32 + kr) * UN + bn * 128 + n4 * 4);
        }
        cp_commit();
    };
    auto compute = [&](int stg) {
        const float* as = As + stg * 128 * ASTR;
        const float* bs = Bs + stg * 32 * BSTR;
#pragma unroll
        for (int ks = 0; ks < 4; ks++) {
            int k0 = ks * 8;
            uint32_t af[2][4];
#pragma unroll
            for (int mt = 0; mt < 2; mt++) {
                const float* p = as + (wm * 32 + mt * 16 + (lane >> 2)) * ASTR + k0 + (lane & 3);
                af[mt][0] = __float_as_uint(p[0]);
                af[mt][1] = __float_as_uint(p[8 * ASTR]);
                af[mt][2] = __float_as_uint(p[4]);
                af[mt][3] = __float_as_uint(p[8 * ASTR + 4]);
            }
#pragma unroll
            for (int nt = 0; nt < 8; nt++) {
                const float* p = bs + (k0 + (lane & 3)) * BSTR + wn * 64 + nt * 8 + (lane >> 2);
                uint32_t bf[2] = { __float_as_uint(p[0]), __float_as_uint(p[4 * BSTR]) };
#pragma unroll
                for (int mt = 0; mt < 2; mt++) mma8(acc[mt][nt], af[mt], bf);
            }
        }
    };

    const int nkb = EE / 32;
    issue(0, 0);
    for (int kb = 0; kb < nkb; kb++) {
        if (kb + 1 < nkb) { issue(kb + 1, (kb + 1) & 1); cp_wait1(); }
        else cp_wait0();
        __syncthreads();
        compute(kb & 1);
        __syncthreads();
    }

#pragma unroll
    for (int mt = 0; mt < 2; mt++)
#pragma unroll
        for (int nt = 0; nt < 8; nt++)
#pragma unroll
            for (int e = 0; e < 4; e++) {
                int r = bm * 128 + wm * 32 + mt * 16 + (lane >> 2) + ((e >> 1) * 8);
                int c = bn * 128 + wn * 64 + nt * 8 + (lane & 3) * 2 + (e & 1);
                float v = acc[mt][nt][e] + beta[c];
                if (c < 1024) v = v / (1.f + __expf(-v));   // silu -> u
                g_uvqk[(size_t)r * UN + c] = tf32r(v);
            }
}

// ---------------- kernel 3: silu attention, double-buffered K/V, P via shfl ---
// per block: (b,h, 128 q-rows). K/V tiles of 64 keys, 2-stage cp.async pipeline.
// P tile never touches smem: score C-frags -> A-frags via index shuffles.
// smem = (128*132 + 2*64*132 + 2*64*132)*4 = 202752 B  (< 232448 B limit)
#define ATTN_SMEM ((128 * 132 + 2 * 64 * 132 + 2 * 64 * 132) * 4)

__global__ __launch_bounds__(256) void attn_k(const int* __restrict__ num_targets) {
    extern __shared__ float sm[];
    float* Qs = sm;                        // 128 x 132
    float* Ks = Qs + 128 * 132;            // 2 stages x 64 x 132
    float* Vs = Ks + 2 * 64 * 132;         // 2 stages x 64 x 132
    const int tid = threadIdx.x, lane = tid & 31, w = tid >> 5;
    const int blk = blockIdx.x;
    const int qt = 15 - (blk & 15);        // heavy causal tiles first (load balance)
    const int bh = blk >> 4, h = bh & 7, b = bh >> 3;
    const int q0 = qt * 128;
    const int T = SS - num_targets[b];

    const float* qbase = g_uvqk + (size_t)(b * SS) * UN + 2048 + h * 128;
    const float* kbase = g_uvqk + (size_t)(b * SS) * UN + 3072 + h * 128;
    const float* vbase = g_uvqk + (size_t)(b * SS) * UN + 1024 + h * 128;

    // load Q tile (128 x 128) -- its own cp.async group
#pragma unroll
    for (int i = 0; i < 16; i++) {
        int c = tid + i * 256; int r = c >> 5, k4 = c & 31;
        cp16(&Qs[r * 132 + k4 * 4], qbase + (size_t)(q0 + r) * UN + k4 * 4);
    }
    cp_commit();

    auto issueKV = [&](int kt, int stg) {
        float* ks = Ks + stg * 64 * 132;
        float* vs = Vs + stg * 64 * 132;
        const int kk0 = kt * 64;
#pragma unroll
        for (int i = 0; i < 8; i++) {
            int c = tid + i * 256; int r = c >> 5, k4 = c & 31;
            cp16(&ks[r * 132 + k4 * 4], kbase + (size_t)(kk0 + r) * UN + k4 * 4);
            cp16(&vs[r * 132 + k4 * 4], vbase + (size_t)(kk0 + r) * UN + k4 * 4);
        }
        cp_commit();
    };

    float acc[16][4];
#pragma unroll
    for (int j = 0; j < 16; j++)
#pragma unroll
        for (int e = 0; e < 4; e++) acc[j][e] = 0.f;

    const int nkt = q0 / 64 + 2;   // causal skip: max needed key <= q0+127
    issueKV(0, 0);                 // prologue: KV tile 0 in flight with Q
    for (int kt = 0; kt < nkt; kt++) {
        const int kk0 = kt * 64;
        const int stg = kt & 1;
        // all warps are done computing on stage (kt+1)&1 -> safe to overwrite
        __syncthreads();
        if (kt + 1 < nkt) { issueKV(kt + 1, (kt + 1) & 1); cp_wait1(); }
        else cp_wait0();
        __syncthreads();           // KV(kt) (and Q on first iter) visible

        const float* KsS = Ks + stg * 64 * 132;
        const float* VsS = Vs + stg * 64 * 132;

        // scores: warp rows [w*16, w*16+16) x 64 keys
        float sc[8][4];
#pragma unroll
        for (int j = 0; j < 8; j++)
#pragma unroll
            for (int e = 0; e < 4; e++) sc[j][e] = 0.f;
#pragma unroll
        for (int ks = 0; ks < 16; ks++) {
            int k0 = ks * 8;
            uint32_t af[4];
            const float* p = Qs + (w * 16 + (lane >> 2)) * 132 + k0 + (lane & 3);
            af[0] = __float_as_uint(p[0]);
            af[1] = __float_as_uint(p[8 * 132]);
            af[2] = __float_as_uint(p[4]);
            af[3] = __float_as_uint(p[8 * 132 + 4]);
#pragma unroll
            for (int nt = 0; nt < 8; nt++) {
                const float* pb = KsS + (nt * 8 + (lane >> 2)) * 132 + k0 + (lane & 3);
                uint32_t bf[2] = { __float_as_uint(pb[0]), __float_as_uint(pb[4]) };
                mma8(sc[nt], af, bf);
            }
        }
        // silu * alpha / S + target-aware causal mask, rounded in-register
#pragma unroll
        for (int nt = 0; nt < 8; nt++)
#pragma unroll
            for (int e = 0; e < 4; e++) {
                int qg = q0 + w * 16 + (lane >> 2) + ((e >> 1) * 8);
                int kg = kk0 + nt * 8 + (lane & 3) * 2 + (e & 1);
                float v = sc[nt][e] * ALPHAV;
                v = v / (1.f + __expf(-v)) * INV_S;
                int idq = min(qg, T), idk = min(kg, T);
                bool msk = (qg == kg) || (idq > idk);
                sc[nt][e] = tf32r(msk ? v : 0.f);
            }
        // attn += P @ V : convert C-frags to A-frags via shuffles, no smem.
        // P(r, k) for k=lane&3 (+4): source lane (lane&~3)|(k>>1), element k&1.
        {
            const int ls  = (lane & ~3) | ((lane & 3) >> 1);
            const int ls2 = ls + 2;
            const bool odd = lane & 1;
#pragma unroll
            for (int ks = 0; ks < 8; ks++) {
                float v0 = __shfl_sync(~0u, sc[ks][0], ls);
                float v1 = __shfl_sync(~0u, sc[ks][1], ls);
                float v2 = __shfl_sync(~0u, sc[ks][2], ls);
                float v3 = __shfl_sync(~0u, sc[ks][3], ls);
                float w0 = __shfl_sync(~0u, sc[ks][0], ls2);
                float w1 = __shfl_sync(~0u, sc[ks][1], ls2);
                float w2 = __shfl_sync(~0u, sc[ks][2], ls2);
                float w3 = __shfl_sync(~0u, sc[ks][3], ls2);
                uint32_t af[4];
                af[0] = __float_as_uint(odd ? v1 : v0);   // (r,   k)
                af[1] = __float_as_uint(odd ? v3 : v2);   // (r+8, k)
                af[2] = __float_as_uint(odd ? w1 : w0);   // (r,   k+4)
                af[3] = __float_as_uint(odd ? w3 : w2);   // (r+8, k+4)
                int k0 = ks * 8;
#pragma unroll
                for (int nt = 0; nt < 16; nt++) {
                    const float* pb = VsS + (k0 + (lane & 3)) * 132 + nt * 8 + (lane >> 2);
                    uint32_t bf[2] = { __float_as_uint(pb[0]), __float_as_uint(pb[4 * 132]) };
                    mma8(acc[nt], af, bf);
                }
            }
        }
    }

#pragma unroll
    for (int nt = 0; nt < 16; nt++)
#pragma unroll
        for (int e = 0; e < 4; e++) {
            int qr = q0 + w * 16 + (lane >> 2) + ((e >> 1) * 8);
            int dc = h * 128 + nt * 8 + (lane & 3) * 2 + (e & 1);
            g_attn[(size_t)(b * SS + qr) * 1024 + dc] = tf32r(acc[nt][e]);
        }
}

// ---------------- kernel 4: LN(attn) * u -> gated ----------------
__global__ __launch_bounds__(256) void ln_gate_k(const float* __restrict__ sc,
                                                 const float* __restrict__ bi) {
    int row = blockIdx.x, t = threadIdx.x;
    const float* ar = g_attn + (size_t)row * 1024;
    float v[4]; float s = 0.f, s2 = 0.f;
#pragma unroll
    for (int i = 0; i < 4; i++) { v[i] = ar[t + i * 256]; s += v[i]; s2 += v[i] * v[i]; }
#pragma unroll
    for (int o = 16; o; o >>= 1) { s += __shfl_xor_sync(~0u, s, o); s2 += __shfl_xor_sync(~0u, s2, o); }
    __shared__ float rs[8], rq[8];
    if ((t & 31) == 0) { rs[t >> 5] = s; rq[t >> 5] = s2; }
    __syncthreads();
    s = 0.f; s2 = 0.f;
#pragma unroll
    for (int i = 0; i < 8; i++) { s += rs[i]; s2 += rq[i]; }
    float mu = s * (1.f / 1024.f);
    float var = s2 * (1.f / 1024.f) - mu * mu;
    float r = rsqrtf(var + EPSV);
#pragma unroll
    for (int i = 0; i < 4; i++) {
        int c = t + i * 256;
        float normed = (v[i] - mu) * r * sc[c] + bi[c];
        float u = g_uvqk[(size_t)row * UN + c];   // silu'd u
        g_gated[(size_t)row * 1024 + c] = tf32r(u * normed);
    }
}

// ---------------- kernel 5: output GEMM (8192x3072 @ 3072x1024) + residual ----
__global__ __launch_bounds__(256) void gemm_out_k(const float* __restrict__ x,
                                                  float* __restrict__ out) {
    extern __shared__ float sm[];
    float* As = sm;
    float* Bs = sm + 2 * 128 * ASTR;
    const int tid = threadIdx.x, lane = tid & 31, w = tid >> 5;
    const int wm = w & 3, wn = w >> 2;
    const int bm = blockIdx.y, bn = blockIdx.x;

    float acc[2][8][4];
#pragma unroll
    for (int i = 0; i < 2; i++)
#pragma unroll
        for (int j = 0; j < 8; j++)
#pragma unroll
            for (int e = 0; e < 4; e++) acc[i][j][e] = 0.f;

    auto issue = [&](int kb, int stg) {
        float* as = As + stg * 128 * ASTR;
        float* bs = Bs + stg * 32 * BSTR;
#pragma unroll
        for (int i = 0; i < 4; i++) {
            int c = tid + i * 256; int r = c >> 3, k4 = c & 7;
            int kg = kb * 32 + k4 * 4;
            int grow = bm * 128 + r;
            const float* src;
            if (kg < 1024)       src = g_uvqk + (size_t)grow * UN + kg;          // u
            else if (kg < 2048)  src = g_attn + (size_t)grow * 1024 + (kg - 1024);
            else                 src = g_gated + (size_t)grow * 1024 + (kg - 2048);
            cp16(as + r * ASTR + k4 * 4, src);
        }
#pragma unroll
        for (int i = 0; i < 4; i++) {
            int c = tid + i * 256; int kr = c >> 5, n4 = c & 31;
            cp16(bs + kr * BSTR + n4 * 4, g_w2 + (size_t)(kb * 32 + kr) * 1024 + bn * 128 + n4 * 4);
        }
        cp_commit();
    };
    auto compute = [&](int stg) {
        const float* as = As + stg * 128 * ASTR;
        const float* bs = Bs + stg * 32 * BSTR;
#pragma unroll
        for (int ks = 0; ks < 4; ks++) {
            int k0 = ks * 8;
            uint32_t af[2][4];
#pragma unroll
            for (int mt = 0; mt < 2; mt++) {
                const float* p = as + (wm * 32 + mt * 16 + (lane >> 2)) * ASTR + k0 + (lane & 3);
                af[mt][0] = __float_as_uint(p[0]);
                af[mt][1] = __float_as_uint(p[8 * ASTR]);
                af[mt][2] = __float_as_uint(p[4]);
                af[mt][3] = __float_as_uint(p[8 * ASTR + 4]);
            }
#pragma unroll
            for (int nt = 0; nt < 8; nt++) {
                const float* p = bs + (k0 + (lane & 3)) * BSTR + wn * 64 + nt * 8 + (lane >> 2);
                uint32_t bf[2] = { __float_as_uint(p[0]), __float_as_uint(p[4 * BSTR]) };
#pragma unroll
                for (int mt = 0; mt < 2; mt++) mma8(acc[mt][nt], af[mt], bf);
            }
        }
    };

    const int nkb = 3072 / 32;   // 96
    issue(0, 0);
    for (int kb = 0; kb < nkb; kb++) {
        if (kb + 1 < nkb) { issue(kb + 1, (kb + 1) & 1); cp_wait1(); }
        else cp_wait0();
        __syncthreads();
        compute(kb & 1);
        __syncthreads();
    }

#pragma unroll
    for (int mt = 0; mt < 2; mt++)
#pragma unroll
        for (int nt = 0; nt < 8; nt++)
#pragma unroll
            for (int e = 0; e < 4; e++) {
                int r = bm * 128 + wm * 32 + mt * 16 + (lane >> 2) + ((e >> 1) * 8);
                int c = bn * 128 + wn * 64 + nt * 8 + (lane & 3) * 2 + (e & 1);
                size_t idx = (size_t)r * 1024 + c;
                out[idx] = x[idx] + acc[mt][nt][e];
            }
}

// ---------------- launch ----------------
extern "C" void kernel_launch(void* const* d_in, const int* in_sizes, int n_in,
                              void* d_out, int out_size) {
    const float* x     = (const float*)d_in[0];
    const int*   ntg   = (const int*)d_in[1];
    const float* w1    = (const float*)d_in[2];
    const float* beta  = (const float*)d_in[3];
    const float* w2    = (const float*)d_in[4];
    const float* insc  = (const float*)d_in[5];
    const float* inb   = (const float*)d_in[6];
    const float* outsc = (const float*)d_in[7];
    const float* outb  = (const float*)d_in[8];
    float* out = (float*)d_out;

    cudaFuncSetAttribute(gemm_uvqk_k, cudaFuncAttributeMaxDynamicSharedMemorySize, GEMM_SMEM);
    cudaFuncSetAttribute(gemm_out_k,  cudaFuncAttributeMaxDynamicSharedMemorySize, GEMM_SMEM);
    cudaFuncSetAttribute(attn_k,      cudaFuncAttributeMaxDynamicSharedMemorySize, ATTN_SMEM);

    round_weights_k<<<4096, 256>>>((const float4*)w1, (const float4*)w2);
    ln_in_k<<<ROWS, 256>>>(x, insc, inb);
    gemm_uvqk_k<<<dim3(UN / 128, ROWS / 128), 256, GEMM_SMEM>>>(beta);
    attn_k<<<NB * NH * (SS / 128), 256, ATTN_SMEM>>>(ntg);
    ln_gate_k<<<ROWS, 256>>>(outsc, outb);
    gemm_out_k<<<dim3(1024 / 128, ROWS / 128), 256, GEMM_SMEM>>>(x, out);
}

// round 13
// speedup vs baseline: 1.0248x; 1.0248x over previous
#include <cuda_runtime.h>
#include <cstdint>

// ---------------- problem constants ----------------
#define NB   4
#define SS   2048
#define EE   1024
#define NH   8
#define HD   128
#define ROWS 8192            // NB*SS
#define UN   4096            // (HD*2+AD*2)*H
#define EPSV 1e-6f
#define ALPHAV 0.08838834764831845f   // 1/sqrt(128)
#define INV_S (1.0f/2048.0f)

// ---------------- scratch (static device memory; allocation-free) ----------------
__device__ float g_xn[ROWS * EE];            // 32 MB  rounded normed x
__device__ float g_uvqk[(size_t)ROWS * UN];  // 128 MB u|v|q|k (u silu'd), tf32-rounded
__device__ float g_attn[ROWS * 1024];        // 32 MB  attention out, rounded
__device__ float g_gated[ROWS * 1024];       // 32 MB  u * LN(attn), rounded
__device__ float g_w1[EE * UN];              // 16 MB  rounded uvqk weight
__device__ float g_w2[3072 * 1024];          // 12 MB  rounded output weight

// ---------------- helpers ----------------
__device__ __forceinline__ float tf32r(float x) {
    uint32_t u; asm("cvt.rna.tf32.f32 %0, %1;" : "=r"(u) : "f"(x));
    return __uint_as_float(u);
}
__device__ __forceinline__ void cp16(void* dst, const void* src) {
    uint32_t d = (uint32_t)__cvta_generic_to_shared(dst);
    asm volatile("cp.async.cg.shared.global [%0], [%1], 16;\n" :: "r"(d), "l"(src));
}
__device__ __forceinline__ void cp_commit() { asm volatile("cp.async.commit_group;\n"); }
__device__ __forceinline__ void cp_wait0()  { asm volatile("cp.async.wait_group 0;\n"); }
__device__ __forceinline__ void cp_wait1()  { asm volatile("cp.async.wait_group 1;\n"); }

__device__ __forceinline__ void mma8(float* c, const uint32_t* a, const uint32_t* b) {
    asm volatile(
        "mma.sync.aligned.m16n8k8.row.col.f32.tf32.tf32.f32 "
        "{%0,%1,%2,%3},{%4,%5,%6,%7},{%8,%9},{%0,%1,%2,%3};\n"
        : "+f"(c[0]), "+f"(c[1]), "+f"(c[2]), "+f"(c[3])
        : "r"(a[0]), "r"(a[1]), "r"(a[2]), "r"(a[3]), "r"(b[0]), "r"(b[1]));
}

// ---------------- kernel 0: round weights to tf32 ----------------
__global__ void round_weights_k(const float4* __restrict__ w1, const float4* __restrict__ w2) {
    int i = blockIdx.x * 256 + threadIdx.x;
    const int n1 = EE * UN / 4;        // 1048576
    const int n2 = 3072 * 1024 / 4;    // 786432
    if (i < n1) {
        float4 v = w1[i];
        v.x = tf32r(v.x); v.y = tf32r(v.y); v.z = tf32r(v.z); v.w = tf32r(v.w);
        ((float4*)g_w1)[i] = v;
    }
    if (i < n2) {
        float4 v = w2[i];
        v.x = tf32r(v.x); v.y = tf32r(v.y); v.z = tf32r(v.z); v.w = tf32r(v.w);
        ((float4*)g_w2)[i] = v;
    }
}

// ---------------- kernel 1: input layernorm ----------------
__global__ __launch_bounds__(256) void ln_in_k(const float* __restrict__ x,
                                               const float* __restrict__ sc,
                                               const float* __restrict__ bi) {
    int row = blockIdx.x, t = threadIdx.x;
    const float* xr = x + (size_t)row * EE;
    float v[4]; float s = 0.f, s2 = 0.f;
#pragma unroll
    for (int i = 0; i < 4; i++) { v[i] = xr[t + i * 256]; s += v[i]; s2 += v[i] * v[i]; }
#pragma unroll
    for (int o = 16; o; o >>= 1) { s += __shfl_xor_sync(~0u, s, o); s2 += __shfl_xor_sync(~0u, s2, o); }
    __shared__ float rs[8], rq[8];
    if ((t & 31) == 0) { rs[t >> 5] = s; rq[t >> 5] = s2; }
    __syncthreads();
    s = 0.f; s2 = 0.f;
#pragma unroll
    for (int i = 0; i < 8; i++) { s += rs[i]; s2 += rq[i]; }
    float mu = s * (1.f / EE);
    float var = s2 * (1.f / EE) - mu * mu;
    float r = rsqrtf(var + EPSV);
#pragma unroll
    for (int i = 0; i < 4; i++) {
        int c = t + i * 256;
        g_xn[(size_t)row * EE + c] = tf32r((v[i] - mu) * r * sc[c] + bi[c]);
    }
}

// ---------------- kernel 2: uvqk GEMM (8192x1024 @ 1024x4096) ----------------
// BM=128 BN=128 BK=32, 256 thr, 8 warps (4m x 2n), warp tile 32x64
#define ASTR 36
#define BSTR 132
#define GEMM_SMEM ((2 * 128 * ASTR + 2 * 32 * BSTR) * 4)   // 70656 B

__global__ __launch_bounds__(256) void gemm_uvqk_k(const float* __restrict__ beta) {
    extern __shared__ float sm[];
    float* As = sm;                      // 2 stages * 128*36
    float* Bs = sm + 2 * 128 * ASTR;     // 2 stages * 32*132
    const int tid = threadIdx.x, lane = tid & 31, w = tid >> 5;
    const int wm = w & 3, wn = w >> 2;
    const int bm = blockIdx.y, bn = blockIdx.x;

    float acc[2][8][4];
#pragma unroll
    for (int i = 0; i < 2; i++)
#pragma unroll
        for (int j = 0; j < 8; j++)
#pragma unroll
            for (int e = 0; e < 4; e++) acc[i][j][e] = 0.f;

    auto issue = [&](int kb, int stg) {
        float* as = As + stg * 128 * ASTR;
        float* bs = Bs + stg * 32 * BSTR;
#pragma unroll
        for (int i = 0; i < 4; i++) {
            int c = tid + i * 256; int r = c >> 3, k4 = c & 7;
            cp16(as + r * ASTR + k4 * 4, g_xn + (size_t)(bm * 128 + r) * EE + kb * 32 + k4 * 4);
        }
#pragma unroll
        for (int i = 0; i < 4; i++) {
            int c = tid + i * 256; int kr = c >> 5, n4 = c & 31;
            cp16(bs + kr * BSTR + n4 * 4, g_w1 + (size_t)(kb * 32 + kr) * UN + bn * 128 + n4 * 4);
        }
        cp_commit();
    };
    auto compute = [&](int stg) {
        const float* as = As + stg * 128 * ASTR;
        const float* bs = Bs + stg * 32 * BSTR;
#pragma unroll
        for (int ks = 0; ks < 4; ks++) {
            int k0 = ks * 8;
            uint32_t af[2][4];
#pragma unroll
            for (int mt = 0; mt < 2; mt++) {
                const float* p = as + (wm * 32 + mt * 16 + (lane >> 2)) * ASTR + k0 + (lane & 3);
                af[mt][0] = __float_as_uint(p[0]);
                af[mt][1] = __float_as_uint(p[8 * ASTR]);
                af[mt][2] = __float_as_uint(p[4]);
                af[mt][3] = __float_as_uint(p[8 * ASTR + 4]);
            }
#pragma unroll
            for (int nt = 0; nt < 8; nt++) {
                const float* p = bs + (k0 + (lane & 3)) * BSTR + wn * 64 + nt * 8 + (lane >> 2);
                uint32_t bf[2] = { __float_as_uint(p[0]), __float_as_uint(p[4 * BSTR]) };
#pragma unroll
                for (int mt = 0; mt < 2; mt++) mma8(acc[mt][nt], af[mt], bf);
            }
        }
    };

    const int nkb = EE / 32;
    issue(0, 0);
    for (int kb = 0; kb < nkb; kb++) {
        if (kb + 1 < nkb) { issue(kb + 1, (kb + 1) & 1); cp_wait1(); }
        else cp_wait0();
        __syncthreads();
        compute(kb & 1);
        __syncthreads();
    }

#pragma unroll
    for (int mt = 0; mt < 2; mt++)
#pragma unroll
        for (int nt = 0; nt < 8; nt++)
#pragma unroll
            for (int e = 0; e < 4; e++) {
                int r = bm * 128 + wm * 32 + mt * 16 + (lane >> 2) + ((e >> 1) * 8);
                int c = bn * 128 + wn * 64 + nt * 8 + (lane & 3) * 2 + (e & 1);
                float v = acc[mt][nt][e] + beta[c];
                if (c < 1024) v = v / (1.f + __expf(-v));   // silu -> u
                g_uvqk[(size_t)r * UN + c] = tf32r(v);
            }
}

// ---------------- kernel 3: silu attention, 512 thr, split-K warps -----------
// per block: (b,h, 128 q-rows). 16 warps: wm=w&7 (16 rows), wk=w>>3 (32-key half).
// K/V tiles of 64 keys, 2-stage cp.async pipeline. P via register shuffles.
// Per-warp acc holds PARTIAL P@V (its key half); epilogue reduces pairs via smem.
// smem = (128*132 + 2*64*132 + 2*64*132)*4 = 202752 B  (< 232448 B limit)
#define ATTN_SMEM ((128 * 132 + 2 * 64 * 132 + 2 * 64 * 132) * 4)

__global__ __launch_bounds__(512) void attn_k(const int* __restrict__ num_targets) {
    extern __shared__ float sm[];
    float* Qs = sm;                        // 128 x 132 (reused as reduction buffer)
    float* Ks = Qs + 128 * 132;            // 2 stages x 64 x 132
    float* Vs = Ks + 2 * 64 * 132;         // 2 stages x 64 x 132
    const int tid = threadIdx.x, lane = tid & 31, w = tid >> 5;
    const int wm = w & 7, wk = w >> 3;
    const int blk = blockIdx.x;
    const int qt = 15 - (blk & 15);        // heavy causal tiles first (load balance)
    const int bh = blk >> 4, h = bh & 7, b = bh >> 3;
    const int q0 = qt * 128;
    const int T = SS - num_targets[b];

    const float* qbase = g_uvqk + (size_t)(b * SS) * UN + 2048 + h * 128;
    const float* kbase = g_uvqk + (size_t)(b * SS) * UN + 3072 + h * 128;
    const float* vbase = g_uvqk + (size_t)(b * SS) * UN + 1024 + h * 128;

    // load Q tile (128 x 128) -- its own cp.async group
#pragma unroll
    for (int i = 0; i < 8; i++) {
        int c = tid + i * 512; int r = c >> 5, k4 = c & 31;
        cp16(&Qs[r * 132 + k4 * 4], qbase + (size_t)(q0 + r) * UN + k4 * 4);
    }
    cp_commit();

    auto issueKV = [&](int kt, int stg) {
        float* ks = Ks + stg * 64 * 132;
        float* vs = Vs + stg * 64 * 132;
        const int kk0 = kt * 64;
#pragma unroll
        for (int i = 0; i < 4; i++) {
            int c = tid + i * 512; int r = c >> 5, k4 = c & 31;
            cp16(&ks[r * 132 + k4 * 4], kbase + (size_t)(kk0 + r) * UN + k4 * 4);
            cp16(&vs[r * 132 + k4 * 4], vbase + (size_t)(kk0 + r) * UN + k4 * 4);
        }
        cp_commit();
    };

    float acc[16][4];                      // partial P@V over this warp's key half
#pragma unroll
    for (int j = 0; j < 16; j++)
#pragma unroll
        for (int e = 0; e < 4; e++) acc[j][e] = 0.f;

    const int nkt = q0 / 64 + 2;   // causal skip: max needed key <= q0+127
    issueKV(0, 0);                 // prologue: KV tile 0 in flight with Q
    for (int kt = 0; kt < nkt; kt++) {
        const int kk0 = kt * 64;
        const int stg = kt & 1;
        __syncthreads();           // all warps done with stage (kt+1)&1
        if (kt + 1 < nkt) { issueKV(kt + 1, (kt + 1) & 1); cp_wait1(); }
        else cp_wait0();
        __syncthreads();           // KV(kt) (and Q on first iter) visible

        const float* KsS = Ks + stg * 64 * 132;
        const float* VsS = Vs + stg * 64 * 132;

        // scores: warp rows [wm*16, wm*16+16) x keys [wk*32, wk*32+32)
        float sc[4][4];
#pragma unroll
        for (int j = 0; j < 4; j++)
#pragma unroll
            for (int e = 0; e < 4; e++) sc[j][e] = 0.f;
#pragma unroll
        for (int ks = 0; ks < 16; ks++) {
            int k0 = ks * 8;
            uint32_t af[4];
            const float* p = Qs + (wm * 16 + (lane >> 2)) * 132 + k0 + (lane & 3);
            af[0] = __float_as_uint(p[0]);
            af[1] = __float_as_uint(p[8 * 132]);
            af[2] = __float_as_uint(p[4]);
            af[3] = __float_as_uint(p[8 * 132 + 4]);
#pragma unroll
            for (int nt = 0; nt < 4; nt++) {
                const float* pb = KsS + (wk * 32 + nt * 8 + (lane >> 2)) * 132 + k0 + (lane & 3);
                uint32_t bf[2] = { __float_as_uint(pb[0]), __float_as_uint(pb[4]) };
                mma8(sc[nt], af, bf);
            }
        }
        // silu * alpha / S + target-aware causal mask, rounded in-register
#pragma unroll
        for (int nt = 0; nt < 4; nt++)
#pragma unroll
            for (int e = 0; e < 4; e++) {
                int qg = q0 + wm * 16 + (lane >> 2) + ((e >> 1) * 8);
                int kg = kk0 + wk * 32 + nt * 8 + (lane & 3) * 2 + (e & 1);
                float v = sc[nt][e] * ALPHAV;
                v = v / (1.f + __expf(-v)) * INV_S;
                int idq = min(qg, T), idk = min(kg, T);
                bool msk = (qg == kg) || (idq > idk);
                sc[nt][e] = tf32r(msk ? v : 0.f);
            }
        // partial P@V over this warp's 32 keys: C-frags -> A-frags via shuffles.
        {
            const int ls  = (lane & ~3) | ((lane & 3) >> 1);
            const int ls2 = ls + 2;
            const bool odd = lane & 1;
#pragma unroll
            for (int ksl = 0; ksl < 4; ksl++) {
                float v0 = __shfl_sync(~0u, sc[ksl][0], ls);
                float v1 = __shfl_sync(~0u, sc[ksl][1], ls);
                float v2 = __shfl_sync(~0u, sc[ksl][2], ls);
                float v3 = __shfl_sync(~0u, sc[ksl][3], ls);
                float w0 = __shfl_sync(~0u, sc[ksl][0], ls2);
                float w1 = __shfl_sync(~0u, sc[ksl][1], ls2);
                float w2 = __shfl_sync(~0u, sc[ksl][2], ls2);
                float w3 = __shfl_sync(~0u, sc[ksl][3], ls2);
                uint32_t af[4];
                af[0] = __float_as_uint(odd ? v1 : v0);   // (r,   k)
                af[1] = __float_as_uint(odd ? v3 : v2);   // (r+8, k)
                af[2] = __float_as_uint(odd ? w1 : w0);   // (r,   k+4)
                af[3] = __float_as_uint(odd ? w3 : w2);   // (r+8, k+4)
                int k0 = wk * 32 + ksl * 8;
#pragma unroll
                for (int nt = 0; nt < 16; nt++) {
                    const float* pb = VsS + (k0 + (lane & 3)) * 132 + nt * 8 + (lane >> 2);
                    uint32_t bf[2] = { __float_as_uint(pb[0]), __float_as_uint(pb[4 * 132]) };
                    mma8(acc[nt], af, bf);
                }
            }
        }
    }

    // epilogue: reduce the two key-half partials (reuse Qs as 8x16x132 buffer)
    __syncthreads();               // all warps done reading Qs/Ks/Vs
    float* Rs = Qs;                // 8 wm-groups x 16 rows x 132 cols
    if (wk == 1) {
#pragma unroll
        for (int nt = 0; nt < 16; nt++)
#pragma unroll
            for (int e = 0; e < 4; e++) {
                int rl = (lane >> 2) + ((e >> 1) * 8);
                int c  = nt * 8 + (lane & 3) * 2 + (e & 1);
                Rs[(wm * 16 + rl) * 132 + c] = acc[nt][e];
            }
    }
    __syncthreads();
    if (wk == 0) {
#pragma unroll
        for (int nt = 0; nt < 16; nt++)
#pragma unroll
            for (int e = 0; e < 4; e++) {
                int rl = (lane >> 2) + ((e >> 1) * 8);
                int c  = nt * 8 + (lane & 3) * 2 + (e & 1);
                float v = acc[nt][e] + Rs[(wm * 16 + rl) * 132 + c];
                int qr = q0 + wm * 16 + rl;
                g_attn[(size_t)(b * SS + qr) * 1024 + h * 128 + c] = tf32r(v);
            }
    }
}

// ---------------- kernel 4: LN(attn) * u -> gated ----------------
__global__ __launch_bounds__(256) void ln_gate_k(const float* __restrict__ sc,
                                                 const float* __restrict__ bi) {
    int row = blockIdx.x, t = threadIdx.x;
    const float* ar = g_attn + (size_t)row * 1024;
    float v[4]; float s = 0.f, s2 = 0.f;
#pragma unroll
    for (int i = 0; i < 4; i++) { v[i] = ar[t + i * 256]; s += v[i]; s2 += v[i] * v[i]; }
#pragma unroll
    for (int o = 16; o; o >>= 1) { s += __shfl_xor_sync(~0u, s, o); s2 += __shfl_xor_sync(~0u, s2, o); }
    __shared__ float rs[8], rq[8];
    if ((t & 31) == 0) { rs[t >> 5] = s; rq[t >> 5] = s2; }
    __syncthreads();
    s = 0.f; s2 = 0.f;
#pragma unroll
    for (int i = 0; i < 8; i++) { s += rs[i]; s2 += rq[i]; }
    float mu = s * (1.f / 1024.f);
    float var = s2 * (1.f / 1024.f) - mu * mu;
    float r = rsqrtf(var + EPSV);
#pragma unroll
    for (int i = 0; i < 4; i++) {
        int c = t + i * 256;
        float normed = (v[i] - mu) * r * sc[c] + bi[c];
        float u = g_uvqk[(size_t)row * UN + c];   // silu'd u
        g_gated[(size_t)row * 1024 + c] = tf32r(u * normed);
    }
}

// ---------------- kernel 5: output GEMM (8192x3072 @ 3072x1024) + residual ----
__global__ __launch_bounds__(256) void gemm_out_k(const float* __restrict__ x,
                                                  float* __restrict__ out) {
    extern __shared__ float sm[];
    float* As = sm;
    float* Bs = sm + 2 * 128 * ASTR;
    const int tid = threadIdx.x, lane = tid & 31, w = tid >> 5;
    const int wm = w & 3, wn = w >> 2;
    const int bm = blockIdx.y, bn = blockIdx.x;

    float acc[2][8][4];
#pragma unroll
    for (int i = 0; i < 2; i++)
#pragma unroll
        for (int j = 0; j < 8; j++)
#pragma unroll
            for (int e = 0; e < 4; e++) acc[i][j][e] = 0.f;

    auto issue = [&](int kb, int stg) {
        float* as = As + stg * 128 * ASTR;
        float* bs = Bs + stg * 32 * BSTR;
#pragma unroll
        for (int i = 0; i < 4; i++) {
            int c = tid + i * 256; int r = c >> 3, k4 = c & 7;
            int kg = kb * 32 + k4 * 4;
            int grow = bm * 128 + r;
            const float* src;
            if (kg < 1024)       src = g_uvqk + (size_t)grow * UN + kg;          // u
            else if (kg < 2048)  src = g_attn + (size_t)grow * 1024 + (kg - 1024);
            else                 src = g_gated + (size_t)grow * 1024 + (kg - 2048);
            cp16(as + r * ASTR + k4 * 4, src);
        }
#pragma unroll
        for (int i = 0; i < 4; i++) {
            int c = tid + i * 256; int kr = c >> 5, n4 = c & 31;
            cp16(bs + kr * BSTR + n4 * 4, g_w2 + (size_t)(kb * 32 + kr) * 1024 + bn * 128 + n4 * 4);
        }
        cp_commit();
    };
    auto compute = [&](int stg) {
        const float* as = As + stg * 128 * ASTR;
        const float* bs = Bs + stg * 32 * BSTR;
#pragma unroll
        for (int ks = 0; ks < 4; ks++) {
            int k0 = ks * 8;
            uint32_t af[2][4];
#pragma unroll
            for (int mt = 0; mt < 2; mt++) {
                const float* p = as + (wm * 32 + mt * 16 + (lane >> 2)) * ASTR + k0 + (lane & 3);
                af[mt][0] = __float_as_uint(p[0]);
                af[mt][1] = __float_as_uint(p[8 * ASTR]);
                af[mt][2] = __float_as_uint(p[4]);
                af[mt][3] = __float_as_uint(p[8 * ASTR + 4]);
            }
#pragma unroll
            for (int nt = 0; nt < 8; nt++) {
                const float* p = bs + (k0 + (lane & 3)) * BSTR + wn * 64 + nt * 8 + (lane >> 2);
                uint32_t bf[2] = { __float_as_uint(p[0]), __float_as_uint(p[4 * BSTR]) };
#pragma unroll
                for (int mt = 0; mt < 2; mt++) mma8(acc[mt][nt], af[mt], bf);
            }
        }
    };

    const int nkb = 3072 / 32;   // 96
    issue(0, 0);
    for (int kb = 0; kb < nkb; kb++) {
        if (kb + 1 < nkb) { issue(kb + 1, (kb + 1) & 1); cp_wait1(); }
        else cp_wait0();
        __syncthreads();
        compute(kb & 1);
        __syncthreads();
    }

#pragma unroll
    for (int mt = 0; mt < 2; mt++)
#pragma unroll
        for (int nt = 0; nt < 8; nt++)
#pragma unroll
            for (int e = 0; e < 4; e++) {
                int r = bm * 128 + wm * 32 + mt * 16 + (lane >> 2) + ((e >> 1) * 8);
                int c = bn * 128 + wn * 64 + nt * 8 + (lane & 3) * 2 + (e & 1);
                size_t idx = (size_t)r * 1024 + c;
                out[idx] = x[idx] + acc[mt][nt][e];
            }
}

// ---------------- launch ----------------
extern "C" void kernel_launch(void* const* d_in, const int* in_sizes, int n_in,
                              void* d_out, int out_size) {
    const float* x     = (const float*)d_in[0];
    const int*   ntg   = (const int*)d_in[1];
    const float* w1    = (const float*)d_in[2];
    const float* beta  = (const float*)d_in[3];
    const float* w2    = (const float*)d_in[4];
    const float* insc  = (const float*)d_in[5];
    const float* inb   = (const float*)d_in[6];
    const float* outsc = (const float*)d_in[7];
    const float* outb  = (const float*)d_in[8];
    float* out = (float*)d_out;

    cudaFuncSetAttribute(gemm_uvqk_k, cudaFuncAttributeMaxDynamicSharedMemorySize, GEMM_SMEM);
    cudaFuncSetAttribute(gemm_out_k,  cudaFuncAttributeMaxDynamicSharedMemorySize, GEMM_SMEM);
    cudaFuncSetAttribute(attn_k,      cudaFuncAttributeMaxDynamicSharedMemorySize, ATTN_SMEM);

    round_weights_k<<<4096, 256>>>((const float4*)w1, (const float4*)w2);
    ln_in_k<<<ROWS, 256>>>(x, insc, inb);
    gemm_uvqk_k<<<dim3(UN / 128, ROWS / 128), 256, GEMM_SMEM>>>(beta);
    attn_k<<<NB * NH * (SS / 128), 512, ATTN_SMEM>>>(ntg);
    ln_gate_k<<<ROWS, 256>>>(outsc, outb);
    gemm_out_k<<<dim3(1024 / 128, ROWS / 128), 256, GEMM_SMEM>>>(x, out);
}